// round 11
// baseline (speedup 1.0000x reference)
#include <cuda_runtime.h>
#include <cuda_bf16.h>
#include <math_constants.h>

// MASS_18897856102446: fused weighted-sq-dist attention
// out[b,n] = out_dist[b,n] * softmax_n(-(att_dist[b,n]*mask[b,n]))
// B=1024, N=200, E=128 (fp32). HBM-bound: m + m_c = ~210MB streamed once.
// R11: cp.async (LDGSTS) shared-memory pipeline. 8-row chunks (8KB: 8 rows m
//      + 8 rows m_c), 3-deep ring buffer, one commit-group per chunk,
//      wait_group 2 + bar per chunk. Loads never occupy registers: 24KB/CTA
//      in flight continuously (register design peaked at 8KB with gaps).
//      Compute: conflict-free LDS.128 row reads, 2 rows/warp/chunk,
//      9-shuffle pair-merging tree. Regs ~45, smem ~28KB -> 7 CTAs/SM,
//      single wave.

constexpr int N_     = 200;
constexpr int E_     = 128;
constexpr int NWARP  = 4;
constexpr int NTHR   = NWARP * 32;     // 128
constexpr int CH     = 8;              // rows per chunk
constexpr int NCHUNK = N_ / CH;        // 25 (exact)
constexpr int DEPTH  = 3;              // pipeline stages
constexpr int ROWB   = E_ * 4;         // 512 B per row
constexpr int CHUNKB = 2 * CH * ROWB;  // 8192 B per stage

__global__ __launch_bounds__(NTHR, 7)
void mass_kernel(const float* __restrict__ q,
                 const float* __restrict__ q_p,
                 const float* __restrict__ m,
                 const float* __restrict__ m_c,
                 const float* __restrict__ A1,
                 const float* __restrict__ A2,
                 const float* __restrict__ biases,
                 const float* __restrict__ mask,
                 float* __restrict__ out)
{
    const int b    = blockIdx.x;
    const int tid  = threadIdx.x;
    const int warp = tid >> 5;
    const int lane = tid & 31;

    __shared__ __align__(16) char s_buf[DEPTH * CHUNKB];   // 24 KB ring
    __shared__ float4 s_v[E_ / 4], s_m2u[E_ / 4];
    __shared__ float  s_cq[NWARP];
    __shared__ float  s_logit[N_], s_outd[N_];
    __shared__ float  s_b2[N_], s_mk[N_];
    __shared__ float  s_red[NWARP];

    const float4* __restrict__ m4 = reinterpret_cast<const float4*>(m   + (size_t)b * N_ * E_);
    const float4* __restrict__ c4 = reinterpret_cast<const float4*>(m_c + (size_t)b * N_ * E_);

    const unsigned sbase = (unsigned)__cvta_generic_to_shared(s_buf);

    // Issue one chunk: 512 x 16B pieces, 4 per thread, coalesced per warp.
    // piece p = i*128 + tid: tensor = p>>8, row = (p>>5)&7, ln = p&31.
    auto issue_chunk = [&](int k) {
        const int slot   = k % DEPTH;
        const int base_n = k * CH;
        #pragma unroll
        for (int i = 0; i < 4; i++) {
            const int p      = i * NTHR + tid;
            const int tensor = p >> 8;
            const int row    = (p >> 5) & 7;
            const int ln     = p & 31;
            const float4* src = (tensor ? c4 : m4)
                              + (size_t)(base_n + row) * (E_ / 4) + ln;
            const unsigned dst = sbase + slot * CHUNKB + tensor * (CH * ROWB)
                               + row * ROWB + ln * 16;
            asm volatile("cp.async.cg.shared.global [%0], [%1], 16;"
                         :: "r"(dst), "l"(src) : "memory");
        }
        asm volatile("cp.async.commit_group;" ::: "memory");
    };

    // Prime the pipeline BEFORE the prologue so DRAM latency overlaps it.
    issue_chunk(0);
    issue_chunk(1);
    issue_chunk(2);

    // Prologue: stage v = a1^2+a2^2, m2u = -2(a1^2 q + a2^2 qp), Cq, 2*bias, mask.
    {
        const float a1 = A1[tid];
        const float a2 = A2[tid];
        const float a1s = a1 * a1, a2s = a2 * a2;
        const float qv  = q  [(size_t)b * E_ + tid];
        const float qpv = q_p[(size_t)b * E_ + tid];
        reinterpret_cast<float*>(s_v)  [tid] = a1s + a2s;
        reinterpret_cast<float*>(s_m2u)[tid] = -2.f * (a1s * qv + a2s * qpv);

        s_b2[tid] = 2.f * biases[(size_t)b * N_ + tid];
        s_mk[tid] = mask  [(size_t)b * N_ + tid];
        if (tid + NTHR < N_) {
            s_b2[tid + NTHR] = 2.f * biases[(size_t)b * N_ + tid + NTHR];
            s_mk[tid + NTHR] = mask  [(size_t)b * N_ + tid + NTHR];
        }

        float c = a1s * qv * qv + a2s * qpv * qpv;
        #pragma unroll
        for (int o = 16; o; o >>= 1)
            c += __shfl_xor_sync(0xffffffffu, c, o);
        if (lane == 0) s_cq[warp] = c;
    }
    __syncthreads();

    const float4 vv = s_v[lane];
    const float4 mu = s_m2u[lane];
    const float  Cq = s_cq[0] + s_cq[1] + s_cq[2] + s_cq[3];

    // sa = sum_e m*(v*m - 2u); so likewise with m_c. 16 FFMA per row.
    auto body = [&](const float4 mv, const float4 cv, float& sa, float& so) {
        float t;
        t = fmaf(vv.x, mv.x, mu.x); sa = mv.x * t;
        t = fmaf(vv.y, mv.y, mu.y); sa = fmaf(mv.y, t, sa);
        t = fmaf(vv.z, mv.z, mu.z); sa = fmaf(mv.z, t, sa);
        t = fmaf(vv.w, mv.w, mu.w); sa = fmaf(mv.w, t, sa);
        t = fmaf(vv.x, cv.x, mu.x); so = cv.x * t;
        t = fmaf(vv.y, cv.y, mu.y); so = fmaf(cv.y, t, so);
        t = fmaf(vv.z, cv.z, mu.z); so = fmaf(cv.z, t, so);
        t = fmaf(vv.w, cv.w, mu.w); so = fmaf(cv.w, t, so);
    };

    const unsigned FULL = 0xffffffffu;
    const bool lo16 = (lane & 16) == 0;
    const bool b3z  = (lane & 8)  == 0;

    // Main pipeline: 25 chunks. Each warp computes rows {2*warp, 2*warp+1}.
    #pragma unroll 1
    for (int k = 0; k < NCHUNK; k++) {
        asm volatile("cp.async.wait_group 2;" ::: "memory");
        __syncthreads();                       // chunk k visible to all warps

        const char* buf = s_buf + (k % DEPTH) * CHUNKB;
        const int r0 = 2 * warp;
        const int r1 = 2 * warp + 1;
        const float4 mv0 = reinterpret_cast<const float4*>(buf + r0 * ROWB)[lane];
        const float4 cv0 = reinterpret_cast<const float4*>(buf + CH * ROWB + r0 * ROWB)[lane];
        const float4 mv1 = reinterpret_cast<const float4*>(buf + r1 * ROWB)[lane];
        const float4 cv1 = reinterpret_cast<const float4*>(buf + CH * ROWB + r1 * ROWB)[lane];

        float sa0, so0, sa1, so1;
        body(mv0, cv0, sa0, so0);
        body(mv1, cv1, sa1, so1);

        // Pair-merging tree: 4 warp-sums in 9 shuffles.
        float A, B;
        A = sa0 + __shfl_xor_sync(FULL, sa0, 16);
        B = so0 + __shfl_xor_sync(FULL, so0, 16);
        const float t0 = lo16 ? A : B;          // row0, type by bit4
        A = sa1 + __shfl_xor_sync(FULL, sa1, 16);
        B = so1 + __shfl_xor_sync(FULL, so1, 16);
        const float t1 = lo16 ? A : B;          // row1

        A = t0 + __shfl_xor_sync(FULL, t0, 8);
        B = t1 + __shfl_xor_sync(FULL, t1, 8);
        float s = b3z ? A : B;                  // row by bit3

        s += __shfl_xor_sync(FULL, s, 4);
        s += __shfl_xor_sync(FULL, s, 2);
        s += __shfl_xor_sync(FULL, s, 1);

        // Writer lanes 0,8,16,24: (type=bit4, row=bit3).
        if ((lane & 7) == 0) {
            const int row = (lane >> 3) & 1;
            const int n   = k * CH + 2 * warp + row;
            const float val = (s + Cq + s_b2[n]) * s_mk[n];
            if (lo16) s_logit[n] = -val;
            else      s_outd[n]  =  val;
        }

        __syncthreads();                        // slot k%DEPTH free to overwrite
        const int kn = k + DEPTH;
        if (kn < NCHUNK) {
            issue_chunk(kn);
        } else {
            asm volatile("cp.async.commit_group;" ::: "memory");  // empty group keeps count
        }
    }

    // Block softmax over N_=200 with 128 threads (all logits visible via the
    // loop's trailing __syncthreads).
    const int  n2ok = (tid + NTHR) < N_;
    const float v1 = s_logit[tid];
    const float v2 = n2ok ? s_logit[tid + NTHR] : -CUDART_INF_F;

    float wm = fmaxf(v1, v2);
    #pragma unroll
    for (int o = 16; o; o >>= 1)
        wm = fmaxf(wm, __shfl_xor_sync(0xffffffffu, wm, o));
    if (lane == 0) s_red[warp] = wm;
    __syncthreads();

    float mx = fmaxf(fmaxf(s_red[0], s_red[1]), fmaxf(s_red[2], s_red[3]));

    const float ex1 = __expf(v1 - mx);
    const float ex2 = n2ok ? __expf(v2 - mx) : 0.f;

    float ws = ex1 + ex2;
    #pragma unroll
    for (int o = 16; o; o >>= 1)
        ws += __shfl_xor_sync(0xffffffffu, ws, o);
    __syncthreads();
    if (lane == 0) s_red[warp] = ws;
    __syncthreads();

    const float inv = 1.f / (s_red[0] + s_red[1] + s_red[2] + s_red[3]);

    out[(size_t)b * N_ + tid] = s_outd[tid] * ex1 * inv;
    if (n2ok)
        out[(size_t)b * N_ + tid + NTHR] = s_outd[tid + NTHR] * ex2 * inv;
}

extern "C" void kernel_launch(void* const* d_in, const int* in_sizes, int n_in,
                              void* d_out, int out_size)
{
    const float* q      = (const float*)d_in[0];
    const float* q_p    = (const float*)d_in[1];
    const float* m      = (const float*)d_in[2];
    const float* m_c    = (const float*)d_in[3];
    const float* A1     = (const float*)d_in[4];
    const float* A2     = (const float*)d_in[5];
    const float* biases = (const float*)d_in[6];
    const float* mask   = (const float*)d_in[7];
    float* out = (float*)d_out;

    const int B = in_sizes[0] / E_;   // 1024
    mass_kernel<<<B, NTHR>>>(q, q_p, m, m_c, A1, A2, biases, mask, out);
}

// round 12
// speedup vs baseline: 1.0191x; 1.0191x over previous
#include <cuda_runtime.h>
#include <cuda_bf16.h>
#include <math_constants.h>

// MASS_18897856102446: fused weighted-sq-dist attention
// out[b,n] = out_dist[b,n] * softmax_n(-(att_dist[b,n]*mask[b,n]))
// B=1024, N=200, E=128 (fp32). HBM-bound: m + m_c = ~210MB streamed once.
// R12: R11 cp.async pipeline with overhead stripped:
//   - ONE barrier per chunk (issue chunk k+2 into slot (k-1)%3 right after
//     the top barrier, which proves all warps finished chunk k-1).
//   - cp.async addressing hoisted: per-thread (tensor,row,lane) decomposition
//     is chunk-invariant; per chunk each copy is 1 IMAD + 1 IADD.
//   25 chunks x 8 rows, 3-deep 24KB ring, 24KB+ in flight continuously.

constexpr int N_     = 200;
constexpr int E_     = 128;
constexpr int NWARP  = 4;
constexpr int NTHR   = NWARP * 32;     // 128
constexpr int CH     = 8;              // rows per chunk
constexpr int NCHUNK = N_ / CH;        // 25 (exact)
constexpr int DEPTH  = 3;              // pipeline stages
constexpr int ROWB   = E_ * 4;         // 512 B per row
constexpr int CHUNKB = 2 * CH * ROWB;  // 8192 B per stage
constexpr int CHSTEP = CH * (E_ / 4);  // float4s per tensor per chunk (256)

__global__ __launch_bounds__(NTHR, 7)
void mass_kernel(const float* __restrict__ q,
                 const float* __restrict__ q_p,
                 const float* __restrict__ m,
                 const float* __restrict__ m_c,
                 const float* __restrict__ A1,
                 const float* __restrict__ A2,
                 const float* __restrict__ biases,
                 const float* __restrict__ mask,
                 float* __restrict__ out)
{
    const int b    = blockIdx.x;
    const int tid  = threadIdx.x;
    const int warp = tid >> 5;
    const int lane = tid & 31;

    __shared__ __align__(16) char s_buf[DEPTH * CHUNKB];   // 24 KB ring
    __shared__ float4 s_v[E_ / 4], s_m2u[E_ / 4];
    __shared__ float  s_cq[NWARP];
    __shared__ float  s_logit[N_], s_outd[N_];
    __shared__ float  s_b2[N_], s_mk[N_];
    __shared__ float  s_red[NWARP];

    const float4* __restrict__ m4 = reinterpret_cast<const float4*>(m   + (size_t)b * N_ * E_);
    const float4* __restrict__ c4 = reinterpret_cast<const float4*>(m_c + (size_t)b * N_ * E_);

    const unsigned sbase = (unsigned)__cvta_generic_to_shared(s_buf);

    // Hoisted per-thread copy descriptors (chunk-invariant).
    // piece p = i*128 + tid: tensor = p>>8, row = (p>>5)&7, ln = p&31.
    const float4* srcb[4];
    unsigned      dsto[4];
    #pragma unroll
    for (int i = 0; i < 4; i++) {
        const int p      = i * NTHR + tid;
        const int tensor = p >> 8;
        const int row    = (p >> 5) & 7;
        const int ln     = p & 31;
        srcb[i] = (tensor ? c4 : m4) + row * (E_ / 4) + ln;
        dsto[i] = sbase + tensor * (CH * ROWB) + row * ROWB + ln * 16;
    }

    // Issue chunk k: 4 cp.async per thread, 1 IMAD + 1 IADD addressing each.
    auto issue_chunk = [&](int k, int slot) {
        const unsigned sb = slot * CHUNKB;
        const int      ks = k * CHSTEP;
        #pragma unroll
        for (int i = 0; i < 4; i++) {
            asm volatile("cp.async.cg.shared.global [%0], [%1], 16;"
                         :: "r"(dsto[i] + sb), "l"(srcb[i] + ks) : "memory");
        }
        asm volatile("cp.async.commit_group;" ::: "memory");
    };

    // Prime chunks 0 and 1 (slots 0, 1) BEFORE the prologue.
    issue_chunk(0, 0);
    issue_chunk(1, 1);

    // Prologue: stage v, m2u, Cq, 2*bias, mask — overlaps primed loads.
    {
        const float a1 = A1[tid];
        const float a2 = A2[tid];
        const float a1s = a1 * a1, a2s = a2 * a2;
        const float qv  = q  [(size_t)b * E_ + tid];
        const float qpv = q_p[(size_t)b * E_ + tid];
        reinterpret_cast<float*>(s_v)  [tid] = a1s + a2s;
        reinterpret_cast<float*>(s_m2u)[tid] = -2.f * (a1s * qv + a2s * qpv);

        s_b2[tid] = 2.f * biases[(size_t)b * N_ + tid];
        s_mk[tid] = mask  [(size_t)b * N_ + tid];
        if (tid + NTHR < N_) {
            s_b2[tid + NTHR] = 2.f * biases[(size_t)b * N_ + tid + NTHR];
            s_mk[tid + NTHR] = mask  [(size_t)b * N_ + tid + NTHR];
        }

        float c = a1s * qv * qv + a2s * qpv * qpv;
        #pragma unroll
        for (int o = 16; o; o >>= 1)
            c += __shfl_xor_sync(0xffffffffu, c, o);
        if (lane == 0) s_cq[warp] = c;
    }
    __syncthreads();

    const float4 vv = s_v[lane];
    const float4 mu = s_m2u[lane];
    const float  Cq = s_cq[0] + s_cq[1] + s_cq[2] + s_cq[3];

    auto body = [&](const float4 mv, const float4 cv, float& sa, float& so) {
        float t;
        t = fmaf(vv.x, mv.x, mu.x); sa = mv.x * t;
        t = fmaf(vv.y, mv.y, mu.y); sa = fmaf(mv.y, t, sa);
        t = fmaf(vv.z, mv.z, mu.z); sa = fmaf(mv.z, t, sa);
        t = fmaf(vv.w, mv.w, mu.w); sa = fmaf(mv.w, t, sa);
        t = fmaf(vv.x, cv.x, mu.x); so = cv.x * t;
        t = fmaf(vv.y, cv.y, mu.y); so = fmaf(cv.y, t, so);
        t = fmaf(vv.z, cv.z, mu.z); so = fmaf(cv.z, t, so);
        t = fmaf(vv.w, cv.w, mu.w); so = fmaf(cv.w, t, so);
    };

    const unsigned FULL = 0xffffffffu;
    const bool lo16 = (lane & 16) == 0;
    const bool b3z  = (lane & 8)  == 0;

    // Single-barrier pipeline:
    //   wait chunk k -> barrier (proves compute k-1 done everywhere)
    //   -> issue chunk k+2 into slot (k+2)%3 (= (k-1)%3, free)
    //   -> compute chunk k.
    int slot = 0;   // slot of chunk k
    #pragma unroll 1
    for (int k = 0; k < NCHUNK; k++) {
        asm volatile("cp.async.wait_group 1;" ::: "memory");
        __syncthreads();

        const int kn = k + 2;
        if (kn < NCHUNK) {
            const int sn = slot + 2 >= DEPTH ? slot + 2 - DEPTH : slot + 2;
            issue_chunk(kn, sn);
        } else {
            asm volatile("cp.async.commit_group;" ::: "memory");
        }

        const char* buf = s_buf + slot * CHUNKB;
        const int r0 = 2 * warp;
        const int r1 = 2 * warp + 1;
        const float4 mv0 = reinterpret_cast<const float4*>(buf + r0 * ROWB)[lane];
        const float4 cv0 = reinterpret_cast<const float4*>(buf + CH * ROWB + r0 * ROWB)[lane];
        const float4 mv1 = reinterpret_cast<const float4*>(buf + r1 * ROWB)[lane];
        const float4 cv1 = reinterpret_cast<const float4*>(buf + CH * ROWB + r1 * ROWB)[lane];

        float sa0, so0, sa1, so1;
        body(mv0, cv0, sa0, so0);
        body(mv1, cv1, sa1, so1);

        // Pair-merging tree: 4 warp-sums in 9 shuffles.
        float A, B;
        A = sa0 + __shfl_xor_sync(FULL, sa0, 16);
        B = so0 + __shfl_xor_sync(FULL, so0, 16);
        const float t0 = lo16 ? A : B;
        A = sa1 + __shfl_xor_sync(FULL, sa1, 16);
        B = so1 + __shfl_xor_sync(FULL, so1, 16);
        const float t1 = lo16 ? A : B;

        A = t0 + __shfl_xor_sync(FULL, t0, 8);
        B = t1 + __shfl_xor_sync(FULL, t1, 8);
        float s = b3z ? A : B;

        s += __shfl_xor_sync(FULL, s, 4);
        s += __shfl_xor_sync(FULL, s, 2);
        s += __shfl_xor_sync(FULL, s, 1);

        if ((lane & 7) == 0) {
            const int row = (lane >> 3) & 1;
            const int n   = k * CH + 2 * warp + row;
            const float val = (s + Cq + s_b2[n]) * s_mk[n];
            if (lo16) s_logit[n] = -val;
            else      s_outd[n]  =  val;
        }

        slot = slot + 1 >= DEPTH ? 0 : slot + 1;
    }
    __syncthreads();   // all logits/outd visible

    // Block softmax over N_=200 with 128 threads.
    const int  n2ok = (tid + NTHR) < N_;
    const float v1 = s_logit[tid];
    const float v2 = n2ok ? s_logit[tid + NTHR] : -CUDART_INF_F;

    float wm = fmaxf(v1, v2);
    #pragma unroll
    for (int o = 16; o; o >>= 1)
        wm = fmaxf(wm, __shfl_xor_sync(0xffffffffu, wm, o));
    if (lane == 0) s_red[warp] = wm;
    __syncthreads();

    float mx = fmaxf(fmaxf(s_red[0], s_red[1]), fmaxf(s_red[2], s_red[3]));

    const float ex1 = __expf(v1 - mx);
    const float ex2 = n2ok ? __expf(v2 - mx) : 0.f;

    float ws = ex1 + ex2;
    #pragma unroll
    for (int o = 16; o; o >>= 1)
        ws += __shfl_xor_sync(0xffffffffu, ws, o);
    __syncthreads();
    if (lane == 0) s_red[warp] = ws;
    __syncthreads();

    const float inv = 1.f / (s_red[0] + s_red[1] + s_red[2] + s_red[3]);

    out[(size_t)b * N_ + tid] = s_outd[tid] * ex1 * inv;
    if (n2ok)
        out[(size_t)b * N_ + tid + NTHR] = s_outd[tid + NTHR] * ex2 * inv;
}

extern "C" void kernel_launch(void* const* d_in, const int* in_sizes, int n_in,
                              void* d_out, int out_size)
{
    const float* q      = (const float*)d_in[0];
    const float* q_p    = (const float*)d_in[1];
    const float* m      = (const float*)d_in[2];
    const float* m_c    = (const float*)d_in[3];
    const float* A1     = (const float*)d_in[4];
    const float* A2     = (const float*)d_in[5];
    const float* biases = (const float*)d_in[6];
    const float* mask   = (const float*)d_in[7];
    float* out = (float*)d_out;

    const int B = in_sizes[0] / E_;   // 1024
    mass_kernel<<<B, NTHR>>>(q, q_p, m, m_c, A1, A2, biases, mask, out);
}